// round 2
// baseline (speedup 1.0000x reference)
#include <cuda_runtime.h>
#include <cstdint>

// Problem dims
#define PD1   128
#define PD2   128
#define PB    16
#define PSIN  64
#define PSOUT 128
// M = PD1*PD2*PB = 262144 rows of the GEMM
// a / h layout: [i][j][b][s] row-major, s fastest. j-stride = PB*PSOUT = 2048 floats.

// ---------------- packed f32x2 helpers ----------------
__device__ __forceinline__ unsigned long long pack2(float x) {
    unsigned int xi = __float_as_uint(x);
    unsigned long long r;
    asm("mov.b64 %0, {%1, %1};" : "=l"(r) : "r"(xi));
    return r;
}
__device__ __forceinline__ void ffma2(unsigned long long &d, unsigned long long a,
                                      unsigned long long b) {
    asm("fma.rn.f32x2 %0, %1, %2, %0;" : "+l"(d) : "l"(a), "l"(b));
}

// ---------------- Kernel 1: a = x @ w + bias  (written into d_out) ----------------
// Block tile: 128 m-rows x 128 n-cols, K=64 processed in two 32-wide phases.
// 128 threads; per-thread micro-tile 8m x 16n (8 f32x2 pairs).
// smem: xs[128][36] (K-half, pad 36 -> 4-bank skew per row), ws[32][128].
#define XS_LD 36
__global__ __launch_bounds__(128)
void mdrnn_gemm_kernel(const float* __restrict__ X, const float* __restrict__ W,
                       const float* __restrict__ Bias, float* __restrict__ A) {
    __shared__ float xs[128 * XS_LD];   // 18432 B
    __shared__ float ws[32 * 128];      // 16384 B

    const int tid   = threadIdx.x;
    const int mtile = blockIdx.x;                 // 2048 tiles of 128 rows
    const float* Xb = X + (size_t)mtile * 128 * PSIN;

    const int warp = tid >> 5;
    const int lane = tid & 31;
    const int tm   = lane >> 3;       // 0..3
    const int tn   = lane & 7;        // 0..7
    const int m0   = warp * 32 + tm;  // + 4*mi  (mi 0..7) -> warp covers 32 rows
    const int n0   = tn * 2;          // + seg*16 (seg 0..7) -> 128 cols

    unsigned long long acc[8][8];
#pragma unroll
    for (int mi = 0; mi < 8; mi++)
#pragma unroll
        for (int seg = 0; seg < 8; seg++) acc[mi][seg] = 0ULL;

    for (int kk = 0; kk < PSIN; kk += 32) {
        __syncthreads();   // previous compute done before overwrite
        // load x half-tile: 128 rows x 32 cols = 1024 float4, 8 per thread
#pragma unroll
        for (int q = 0; q < 8; q++) {
            int id  = tid + 128 * q;
            int row = id >> 3;
            int kq  = id & 7;
            float4 v = *(const float4*)(Xb + row * PSIN + kk + kq * 4);
            float* p = &xs[row * XS_LD + kq * 4];
            *(float4*)p = v;
        }
        // load w half-tile: 32 rows x 128 cols = 1024 float4, 8 per thread
#pragma unroll
        for (int q = 0; q < 8; q++) {
            int id = tid + 128 * q;
            int k  = id >> 5;
            int nq = id & 31;
            *(float4*)&ws[k * 128 + nq * 4] =
                *(const float4*)(W + (size_t)(kk + k) * PSOUT + nq * 4);
        }
        __syncthreads();

#pragma unroll 2
        for (int k = 0; k < 32; k++) {
            unsigned long long wv[8];
#pragma unroll
            for (int seg = 0; seg < 8; seg++)
                wv[seg] = *(const unsigned long long*)&ws[k * 128 + n0 + seg * 16];
#pragma unroll
            for (int mi = 0; mi < 8; mi++) {
                float xv = xs[(m0 + 4 * mi) * XS_LD + k];
                unsigned long long xp = pack2(xv);
#pragma unroll
                for (int seg = 0; seg < 8; seg++) ffma2(acc[mi][seg], xp, wv[seg]);
            }
        }
    }

    // epilogue: + bias, store float2
    float2 bv[8];
#pragma unroll
    for (int seg = 0; seg < 8; seg++)
        bv[seg] = *(const float2*)(Bias + n0 + seg * 16);

#pragma unroll
    for (int mi = 0; mi < 8; mi++) {
        int m = m0 + 4 * mi;
        float* out = A + ((size_t)mtile * 128 + m) * PSOUT;
#pragma unroll
        for (int seg = 0; seg < 8; seg++) {
            uint2 u = *(uint2*)&acc[mi][seg];
            float2 o;
            o.x = __uint_as_float(u.x) + bv[seg].x;
            o.y = __uint_as_float(u.y) + bv[seg].y;
            *(float2*)(out + n0 + seg * 16) = o;
        }
    }
}

// ---------------- Kernel 2: 2D recurrence, wavefront, in place ----------------
// Block = (b, 8-wide s chunk): 16*16 = 256 blocks, 1024 threads = 128 i x 8 s.
// 256 diagonal steps; h[i-1][j] exchanged via double-buffered smem.
__global__ __launch_bounds__(1024, 2)
void mdrnn_scan_kernel(const float* __restrict__ U, float* __restrict__ H) {
    __shared__ float sh[2][1024];

    const int tid = threadIdx.x;
    const int i   = tid >> 3;          // row 0..127
    const int s   = tid & 7;
    const int b   = blockIdx.x >> 4;   // 0..15
    const int chk = blockIdx.x & 15;   // 0..15
    const int sg  = chk * 8 + s;       // global s

    const float u0 = U[sg];
    const float u1 = U[PSOUT + sg];

    const size_t bi = (size_t)i * (PD2 * PB * PSOUT) + (size_t)b * PSOUT + sg; // j=0
    // prefetch pipeline: r0..r3 hold a[i][j..j+3][b][sg]
    float r0 = H[bi];
    float r1 = H[bi + 1 * 2048];
    float r2 = H[bi + 2 * 2048];
    float r3 = H[bi + 3 * 2048];
    float hl = 0.0f;

#pragma unroll 2
    for (int t = 0; t < 256; t++) {
        const int j = t - i;
        if ((unsigned)j < 128u) {
            float hup = 0.0f;
            if (i > 0) hup = sh[(t & 1) ^ 1][tid - 8];
            float z = fmaf(hup, u0, r0);
            z = fmaf(hl, u1, z);
            // tanh(z) = 1 - 2/(exp(2z)+1), via MUFU ex2 + rcp (err ~1e-6)
            float e;
            asm("ex2.approx.f32 %0, %1;" : "=f"(e) : "f"(z * 2.8853900817779268f));
            float rc;
            asm("rcp.approx.f32 %0, %1;" : "=f"(rc) : "f"(e + 1.0f));
            float h = fmaf(-2.0f, rc, 1.0f);
            hl = h;
            sh[t & 1][tid] = h;
            H[bi + (size_t)j * 2048] = h;
            // shift prefetch registers, fetch j+4
            r0 = r1; r1 = r2; r2 = r3;
            int j4 = j + 4;
            r3 = (j4 < 128) ? H[bi + (size_t)j4 * 2048] : 0.0f;
        }
        __syncthreads();
    }
}

// ---------------- launch ----------------
extern "C" void kernel_launch(void* const* d_in, const int* in_sizes, int n_in,
                              void* d_out, int out_size) {
    const float* X    = (const float*)d_in[0];   // (128,128,16,64)
    const float* W    = (const float*)d_in[1];   // (64,128)
    const float* U    = (const float*)d_in[2];   // (2,128)
    const float* Bias = (const float*)d_in[3];   // (128,)
    float* H = (float*)d_out;                    // (128,128,16,128) — holds a, then h

    (void)in_sizes; (void)n_in; (void)out_size;

    mdrnn_gemm_kernel<<<2048, 128>>>(X, W, Bias, H);
    mdrnn_scan_kernel<<<256, 1024>>>(U, H);
}